// round 1
// baseline (speedup 1.0000x reference)
#include <cuda_runtime.h>
#include <cstddef>

// GraphConvMapperBlock: fused edge-MLP + segment-sum + node-MLPs, fp32 exact.
// Round 1: f32x2 packed-FMA GEMM tiles (128x128 per block, 8x8 per thread).

#define CC  128   // channels
#define MT  128   // rows (edges/nodes) per block tile
#define KC  32    // K chunk staged in shared
#define NTH 256

// Aggregator for segment_sum over dst nodes (zeroed every launch).
__device__ float g_agg[40000 * CC];

__device__ __forceinline__ unsigned long long pack2(float x, float y) {
    unsigned long long r;
    asm("mov.b64 %0, {%1,%2};" : "=l"(r) : "f"(x), "f"(y));
    return r;
}
__device__ __forceinline__ void unpack2(unsigned long long v, float& x, float& y) {
    asm("mov.b64 {%0,%1}, %2;" : "=f"(x), "=f"(y) : "l"(v));
}
__device__ __forceinline__ void fma2(unsigned long long& acc, unsigned long long a,
                                     unsigned long long b) {
    asm("fma.rn.f32x2 %0, %1, %2, %0;" : "+l"(acc) : "l"(a), "l"(b));
}

// Dynamic shared layout (floats):
//   [0, 16384)        : Hs  [128][128]  (phase2 A)   -- aliases phase1 As/Bs
//     [0, 4096)       : As  [KC][MT]    (phase1 A chunk)
//     [4096, 8192)    : Bs  [KC][CC]    (phase1 B chunk)
//   [16384, 20480)    : Bs2 [KC][CC]    (phase2 B chunk)
#define SMEM_FLOATS (CC * MT + KC * CC)
#define SMEM_BYTES  (SMEM_FLOATS * 4)

template<int SEGS, bool EDGE>
__global__ __launch_bounds__(NTH, 2)
void mlp_kernel(const float* __restrict__ seg0, const int* __restrict__ idx0,
                const float* __restrict__ seg1, const int* __restrict__ idx1,
                const float* __restrict__ seg2,
                const float* __restrict__ W1, const float* __restrict__ B1,
                const float* __restrict__ W2, const float* __restrict__ B2,
                const float* __restrict__ G,  const float* __restrict__ BN,
                const float* __restrict__ resid,
                const int* __restrict__ aggidx,
                float* __restrict__ agg,
                float* __restrict__ out, int M)
{
    extern __shared__ float smem[];
    float* Hs  = smem;
    float* As  = smem;
    float* Bs  = smem + KC * MT;
    float* Bs2 = smem + CC * MT;

    __shared__ int srow0[MT];
    __shared__ int srow1[MT];
    __shared__ int sagg[MT];

    const int tid   = threadIdx.x;
    const int tile0 = blockIdx.x * MT;
    const int rg = tid >> 4;            // 0..15 row group
    const int cg = tid & 15;            // 0..15 col group
    const int r0 = rg * 8;
    const int c0 = cg * 8;

    if (tid < MT) {
        int r = tile0 + tid;
        bool v = r < M;
        int rr = v ? r : 0;
        srow0[tid] = idx0 ? (v ? idx0[rr] : 0) : rr;
        srow1[tid] = idx1 ? (v ? idx1[rr] : 0) : rr;
        if (EDGE) sagg[tid] = v ? aggidx[rr] : 0;
    }

    unsigned long long acc[8][4];
#pragma unroll
    for (int i = 0; i < 8; i++)
#pragma unroll
        for (int j = 0; j < 4; j++) acc[i][j] = 0ULL;

    __syncthreads();

    // ---------------- Phase 1: [MT, SEGS*128] @ W1 -> hidden [MT, 128] ----
    const int NCHUNK = (SEGS * CC) / KC;
    for (int kc = 0; kc < NCHUNK; ++kc) {
        const int k0  = kc * KC;
        const int seg = k0 >> 7;
        const int off = k0 & 127;
        const float* base = (seg == 0) ? seg0 : ((seg == 1) ? seg1 : seg2);
        const int* srow = (seg == 0) ? srow0 : ((seg == 1) ? srow1 : nullptr);

        // Load A chunk: 128 rows x 32 k (gathered)
        {
            const int q  = tid & 7;    // which float4 of the 32-float chunk
            const int m0 = tid >> 3;   // 0..31
#pragma unroll
            for (int s = 0; s < 4; s++) {
                int m = m0 + 32 * s;
                int row;
                if (srow) row = srow[m];
                else { int r = tile0 + m; row = (r < M) ? r : 0; }
                float4 v = __ldg((const float4*)(base + (size_t)row * CC + off + q * 4));
                float* dst = As + (q * 4) * MT + m;
                dst[0 * MT] = v.x; dst[1 * MT] = v.y; dst[2 * MT] = v.z; dst[3 * MT] = v.w;
            }
        }
        // Load B chunk: W1[k0..k0+31][0..127]
        {
            const int c4  = tid & 31;
            const int kk0 = tid >> 5;
#pragma unroll
            for (int s = 0; s < 4; s++) {
                int kk = kk0 + 8 * s;
                float4 v = __ldg((const float4*)(W1 + (size_t)(k0 + kk) * CC + c4 * 4));
                *(float4*)(Bs + kk * CC + c4 * 4) = v;
            }
        }
        __syncthreads();

#pragma unroll
        for (int kk = 0; kk < KC; kk++) {
            float a[8];
            *(float4*)&a[0] = *(const float4*)(As + kk * MT + r0);
            *(float4*)&a[4] = *(const float4*)(As + kk * MT + r0 + 4);
            unsigned long long b[4];
            {
                const ulonglong2 b01 = *(const ulonglong2*)(Bs + kk * CC + c0);
                const ulonglong2 b23 = *(const ulonglong2*)(Bs + kk * CC + c0 + 4);
                b[0] = b01.x; b[1] = b01.y; b[2] = b23.x; b[3] = b23.y;
            }
#pragma unroll
            for (int i = 0; i < 8; i++) {
                unsigned long long aa = pack2(a[i], a[i]);
                fma2(acc[i][0], aa, b[0]);
                fma2(acc[i][1], aa, b[1]);
                fma2(acc[i][2], aa, b[2]);
                fma2(acc[i][3], aa, b[3]);
            }
        }
        __syncthreads();
    }

    // bias1 + SiLU, transpose hidden into Hs[k][m]
    {
        float b1v[8];
        *(float4*)&b1v[0] = __ldg((const float4*)(B1 + c0));
        *(float4*)&b1v[4] = __ldg((const float4*)(B1 + c0 + 4));
#pragma unroll
        for (int i = 0; i < 8; i++) {
#pragma unroll
            for (int j = 0; j < 4; j++) {
                float x0, x1;
                unpack2(acc[i][j], x0, x1);
                x0 += b1v[2 * j];
                x1 += b1v[2 * j + 1];
                x0 = __fdividef(x0, 1.0f + __expf(-x0));
                x1 = __fdividef(x1, 1.0f + __expf(-x1));
                Hs[(c0 + 2 * j)     * MT + (r0 + i)] = x0;
                Hs[(c0 + 2 * j + 1) * MT + (r0 + i)] = x1;
                acc[i][j] = 0ULL;
            }
        }
    }
    __syncthreads();

    // ---------------- Phase 2: hidden [MT,128] @ W2 -> y [MT,128] ---------
    for (int kc = 0; kc < CC / KC; ++kc) {
        const int k0 = kc * KC;
        {
            const int c4  = tid & 31;
            const int kk0 = tid >> 5;
#pragma unroll
            for (int s = 0; s < 4; s++) {
                int kk = kk0 + 8 * s;
                float4 v = __ldg((const float4*)(W2 + (size_t)(k0 + kk) * CC + c4 * 4));
                *(float4*)(Bs2 + kk * CC + c4 * 4) = v;
            }
        }
        __syncthreads();

#pragma unroll
        for (int kk = 0; kk < KC; kk++) {
            float a[8];
            *(float4*)&a[0] = *(const float4*)(Hs + (k0 + kk) * MT + r0);
            *(float4*)&a[4] = *(const float4*)(Hs + (k0 + kk) * MT + r0 + 4);
            unsigned long long b[4];
            {
                const ulonglong2 b01 = *(const ulonglong2*)(Bs2 + kk * CC + c0);
                const ulonglong2 b23 = *(const ulonglong2*)(Bs2 + kk * CC + c0 + 4);
                b[0] = b01.x; b[1] = b01.y; b[2] = b23.x; b[3] = b23.y;
            }
#pragma unroll
            for (int i = 0; i < 8; i++) {
                unsigned long long aa = pack2(a[i], a[i]);
                fma2(acc[i][0], aa, b[0]);
                fma2(acc[i][1], aa, b[1]);
                fma2(acc[i][2], aa, b[2]);
                fma2(acc[i][3], aa, b[3]);
            }
        }
        __syncthreads();
    }

    // ---------------- Epilogue: bias2 + LayerNorm (+residual / +atomics) --
    {
        float b2v[8], gv[8], bnv[8];
        *(float4*)&b2v[0] = __ldg((const float4*)(B2 + c0));
        *(float4*)&b2v[4] = __ldg((const float4*)(B2 + c0 + 4));
        *(float4*)&gv[0]  = __ldg((const float4*)(G + c0));
        *(float4*)&gv[4]  = __ldg((const float4*)(G + c0 + 4));
        *(float4*)&bnv[0] = __ldg((const float4*)(BN + c0));
        *(float4*)&bnv[4] = __ldg((const float4*)(BN + c0 + 4));

#pragma unroll
        for (int i = 0; i < 8; i++) {
            float y[8];
#pragma unroll
            for (int j = 0; j < 4; j++) {
                unpack2(acc[i][j], y[2 * j], y[2 * j + 1]);
            }
#pragma unroll
            for (int j = 0; j < 8; j++) y[j] += b2v[j];

            float s = 0.f, ss = 0.f;
#pragma unroll
            for (int j = 0; j < 8; j++) { s += y[j]; ss += y[j] * y[j]; }
            // reduce over the 16 col-group lanes (stays inside 16-lane halves)
#pragma unroll
            for (int o = 1; o < 16; o <<= 1) {
                s  += __shfl_xor_sync(0xffffffffu, s,  o);
                ss += __shfl_xor_sync(0xffffffffu, ss, o);
            }
            float mu  = s * (1.0f / 128.0f);
            float var = ss * (1.0f / 128.0f) - mu * mu;
            float rs  = rsqrtf(var + 1e-5f);

            int row = tile0 + r0 + i;
            if (row < M) {
                float vout[8];
#pragma unroll
                for (int j = 0; j < 8; j++)
                    vout[j] = (y[j] - mu) * rs * gv[j] + bnv[j];

                if (!EDGE) {
                    float4 rv0 = __ldg((const float4*)(resid + (size_t)row * CC + c0));
                    float4 rv1 = __ldg((const float4*)(resid + (size_t)row * CC + c0 + 4));
                    vout[0] += rv0.x; vout[1] += rv0.y; vout[2] += rv0.z; vout[3] += rv0.w;
                    vout[4] += rv1.x; vout[5] += rv1.y; vout[6] += rv1.z; vout[7] += rv1.w;
                }
                *(float4*)(out + (size_t)row * CC + c0) =
                    make_float4(vout[0], vout[1], vout[2], vout[3]);
                *(float4*)(out + (size_t)row * CC + c0 + 4) =
                    make_float4(vout[4], vout[5], vout[6], vout[7]);

                if (EDGE) {
                    int d = sagg[r0 + i];
                    float* ap = agg + (size_t)d * CC + c0;
#pragma unroll
                    for (int j = 0; j < 8; j++) atomicAdd(ap + j, vout[j]);
                }
            }
        }
    }
}

__global__ void zero4_kernel(float4* __restrict__ p, int n4) {
    int i = blockIdx.x * blockDim.x + threadIdx.x;
    if (i < n4) p[i] = make_float4(0.f, 0.f, 0.f, 0.f);
}

extern "C" void kernel_launch(void* const* d_in, const int* in_sizes, int n_in,
                              void* d_out, int out_size)
{
    const float* x_src     = (const float*)d_in[0];
    const float* x_dst     = (const float*)d_in[1];
    const float* edge_attr = (const float*)d_in[2];
    const int*   edge_idx  = (const int*)d_in[3];
    const float* ew1 = (const float*)d_in[4];
    const float* eb1 = (const float*)d_in[5];
    const float* ew2 = (const float*)d_in[6];
    const float* eb2 = (const float*)d_in[7];
    const float* eg  = (const float*)d_in[8];
    const float* ebn = (const float*)d_in[9];
    const float* nw1 = (const float*)d_in[10];
    const float* nb1 = (const float*)d_in[11];
    const float* nw2 = (const float*)d_in[12];
    const float* nb2 = (const float*)d_in[13];
    const float* ng  = (const float*)d_in[14];
    const float* nbn = (const float*)d_in[15];

    const int n_src   = in_sizes[0] / CC;
    const int n_dst   = in_sizes[1] / CC;
    const int n_edges = in_sizes[2] / CC;

    const int* src_idx = edge_idx;              // edge_index[0]
    const int* dst_idx = edge_idx + n_edges;    // edge_index[1]

    float* out_src  = (float*)d_out;
    float* out_dst  = out_src + (size_t)n_src * CC;
    float* out_edge = out_dst + (size_t)n_dst * CC;

    float* agg = nullptr;
    cudaGetSymbolAddress((void**)&agg, g_agg);

    cudaFuncSetAttribute(mlp_kernel<3, true>,
                         cudaFuncAttributeMaxDynamicSharedMemorySize, SMEM_BYTES);
    cudaFuncSetAttribute(mlp_kernel<2, false>,
                         cudaFuncAttributeMaxDynamicSharedMemorySize, SMEM_BYTES);

    // 1) zero aggregator
    {
        int n4 = (n_dst * CC) / 4;
        zero4_kernel<<<(n4 + 255) / 256, 256>>>((float4*)agg, n4);
    }
    // 2) edge MLP + scatter-add into agg
    {
        int nb = (n_edges + MT - 1) / MT;
        mlp_kernel<3, true><<<nb, NTH, SMEM_BYTES>>>(
            x_dst, dst_idx, x_src, src_idx, edge_attr,
            ew1, eb1, ew2, eb2, eg, ebn,
            nullptr, dst_idx, agg, out_edge, n_edges);
    }
    // 3) dst node MLP on [x_dst | agg] + residual
    {
        int nb = (n_dst + MT - 1) / MT;
        mlp_kernel<2, false><<<nb, NTH, SMEM_BYTES>>>(
            x_dst, nullptr, agg, nullptr, nullptr,
            nw1, nb1, nw2, nb2, ng, nbn,
            x_dst, nullptr, nullptr, out_dst, n_dst);
    }
    // 4) src node MLP on [x_src | x_src] + residual
    {
        int nb = (n_src + MT - 1) / MT;
        mlp_kernel<2, false><<<nb, NTH, SMEM_BYTES>>>(
            x_src, nullptr, x_src, nullptr, nullptr,
            nw1, nb1, nw2, nb2, ng, nbn,
            x_src, nullptr, nullptr, out_src, n_src);
    }
}

// round 4
// speedup vs baseline: 1.9275x; 1.9275x over previous
#include <cuda_runtime.h>
#include <cuda_bf16.h>
#include <cstdint>
#include <cstddef>

#define CC  128
#define MT  128
#define NTH 256

// ---------------- dynamic SMEM layout (bytes) ------------------------------
// Hs: hidden planes, 128 rows x 256B (swizzled)    -> 32768 each
// A/B chunk planes: 128 rows x 80B (pad stride)    -> 10240 each
#define OF_HS_HI 0u
#define OF_HS_LO 32768u
#define OF_A_HI  65536u
#define OF_A_LO  75776u
#define OF_B_HI  86016u
#define OF_B_LO  96256u
#define SMEM_BYTES 106496u

// -------------------- device globals (no allocations allowed) --------------
__device__ float g_agg[40000 * CC];
__device__ __align__(16) __nv_bfloat16 g_e1hi[CC * 3 * CC], g_e1lo[CC * 3 * CC];
__device__ __align__(16) __nv_bfloat16 g_e2hi[CC * CC],     g_e2lo[CC * CC];
__device__ __align__(16) __nv_bfloat16 g_n1hi[CC * 2 * CC], g_n1lo[CC * 2 * CC];
__device__ __align__(16) __nv_bfloat16 g_n2hi[CC * CC],     g_n2lo[CC * CC];

// -------------------- helpers ----------------------------------------------
__device__ __forceinline__ uint32_t su32(const void* p) {
    return (uint32_t)__cvta_generic_to_shared(p);
}
__device__ __forceinline__ void ldsm4(uint32_t addr, uint32_t& r0, uint32_t& r1,
                                      uint32_t& r2, uint32_t& r3) {
    asm volatile("ldmatrix.sync.aligned.m8n8.x4.shared.b16 {%0,%1,%2,%3}, [%4];"
                 : "=r"(r0), "=r"(r1), "=r"(r2), "=r"(r3) : "r"(addr));
}
__device__ __forceinline__ void mma16816(float* c, const uint32_t* a, const uint32_t* b) {
    asm volatile(
        "mma.sync.aligned.m16n8k16.row.col.f32.bf16.bf16.f32 "
        "{%0,%1,%2,%3}, {%4,%5,%6,%7}, {%8,%9}, {%0,%1,%2,%3};"
        : "+f"(c[0]), "+f"(c[1]), "+f"(c[2]), "+f"(c[3])
        : "r"(a[0]), "r"(a[1]), "r"(a[2]), "r"(a[3]), "r"(b[0]), "r"(b[1]));
}
// pack two floats into bf16x2 hi word; residuals into lo word
__device__ __forceinline__ uint32_t pk2(float x0, float x1, uint32_t& lo) {
    __nv_bfloat16 h0 = __float2bfloat16(x0);
    __nv_bfloat16 h1 = __float2bfloat16(x1);
    float r0 = x0 - __bfloat162float(h0);
    float r1 = x1 - __bfloat162float(h1);
    __nv_bfloat16 l0 = __float2bfloat16(r0);
    __nv_bfloat16 l1 = __float2bfloat16(r1);
    lo = (uint32_t)__bfloat16_as_ushort(l0) | ((uint32_t)__bfloat16_as_ushort(l1) << 16);
    return (uint32_t)__bfloat16_as_ushort(h0) | ((uint32_t)__bfloat16_as_ushort(h1) << 16);
}
__device__ __forceinline__ void split8(float4 a, float4 b, uint4& hi, uint4& lo) {
    uint32_t l0, l1, l2, l3;
    hi.x = pk2(a.x, a.y, l0);
    hi.y = pk2(a.z, a.w, l1);
    hi.z = pk2(b.x, b.y, l2);
    hi.w = pk2(b.z, b.w, l3);
    lo = make_uint4(l0, l1, l2, l3);
}

// -------------------- fused MLP kernel (mma.sync bf16, 3-term split) -------
template<int SEGS, bool EDGE>
__global__ __launch_bounds__(NTH, 2)
void mlp_mma(const float* __restrict__ seg0, const int* __restrict__ idx0,
             const float* __restrict__ seg1, const int* __restrict__ idx1,
             const float* __restrict__ seg2,
             const __nv_bfloat16* __restrict__ W1hi, const __nv_bfloat16* __restrict__ W1lo,
             const __nv_bfloat16* __restrict__ W2hi, const __nv_bfloat16* __restrict__ W2lo,
             const float* __restrict__ B1, const float* __restrict__ B2,
             const float* __restrict__ G,  const float* __restrict__ BN,
             const float* __restrict__ resid,
             const int* __restrict__ aggidx, float* __restrict__ agg,
             float* __restrict__ out, int M)
{
    extern __shared__ __align__(16) char dsm[];
    __shared__ int srow[3][MT];
    __shared__ int saggi[MT];
    __shared__ float sB1[CC], sB2[CC], sG[CC], sBN[CC];

    const int tid  = threadIdx.x;
    const int wid  = tid >> 5;
    const int lane = tid & 31;
    const int wm   = wid & 1;        // 2 row-groups of 64
    const int wn   = wid >> 1;       // 4 col-groups of 32
    const int tile0 = blockIdx.x * MT;
    const int K1 = SEGS * CC;
    const uint32_t sbase = su32(dsm);

    if (tid < MT) {
        int r = tile0 + tid;
        int rr = (r < M) ? r : (M - 1);
        srow[0][tid] = idx0 ? idx0[rr] : rr;
        srow[1][tid] = idx1 ? idx1[rr] : rr;
        srow[2][tid] = rr;
        if (EDGE) saggi[tid] = aggidx[rr];
        sB1[tid] = B1[tid]; sB2[tid] = B2[tid];
        sG[tid]  = G[tid];  sBN[tid] = BN[tid];
    }

    float acc[4][4][4];
#pragma unroll
    for (int i = 0; i < 4; i++)
#pragma unroll
        for (int j = 0; j < 4; j++)
#pragma unroll
            for (int k = 0; k < 4; k++) acc[i][j][k] = 0.f;

    __syncthreads();

    const int r16 = lane & 15;             // ldmatrix row within 16
    const int cq  = (lane >> 4) << 3;      // ldmatrix col half (0 or 8)

    // ================= GEMM1: [128, SEGS*128] @ W1 =========================
    for (int c = 0; c < SEGS * 4; ++c) {
        const int k0  = c * 32;
        const int sg  = k0 >> 7;
        const int off = k0 & 127;
        const float* base = (sg == 0) ? seg0 : ((sg == 1) ? seg1 : seg2);
        const int*   srw  = srow[sg];

        // ---- stage A chunk: gathered fp32 -> bf16 hi/lo, rows stride 80B
        {
            const int m = tid >> 1, h = tid & 1;
            const float* p = base + (size_t)srw[m] * CC + off + h * 16;
            float4 v0 = __ldg((const float4*)p);
            float4 v1 = __ldg((const float4*)p + 1);
            float4 v2 = __ldg((const float4*)p + 2);
            float4 v3 = __ldg((const float4*)p + 3);
            uint4 HI, LO;
            char* dh = dsm + OF_A_HI + m * 80 + h * 32;
            char* dl = dsm + OF_A_LO + m * 80 + h * 32;
            split8(v0, v1, HI, LO);
            *(uint4*)dh = HI; *(uint4*)dl = LO;
            split8(v2, v3, HI, LO);
            *(uint4*)(dh + 16) = HI; *(uint4*)(dl + 16) = LO;
        }
        // ---- stage B chunk: pre-split W1 planes [n][K1], straight copy
        {
            const int n = tid >> 1, h = tid & 1;
            const __nv_bfloat16* ph = W1hi + (size_t)n * K1 + k0 + h * 16;
            const __nv_bfloat16* pl = W1lo + (size_t)n * K1 + k0 + h * 16;
            char* dh = dsm + OF_B_HI + n * 80 + h * 32;
            char* dl = dsm + OF_B_LO + n * 80 + h * 32;
            *(uint4*)dh        = __ldg((const uint4*)ph);
            *(uint4*)(dh + 16) = __ldg((const uint4*)ph + 1);
            *(uint4*)dl        = __ldg((const uint4*)pl);
            *(uint4*)(dl + 16) = __ldg((const uint4*)pl + 1);
        }
        __syncthreads();

#pragma unroll
        for (int ks = 0; ks < 2; ++ks) {
            const int kk = ks * 16;
            uint32_t ah[4][4], bh[4][2], bl[4][2];
#pragma unroll
            for (int nb = 0; nb < 2; ++nb) {
                const int n0 = wn * 32 + nb * 16;
                uint32_t t0, t1, t2, t3;
                ldsm4(sbase + OF_B_HI + (n0 + r16) * 80 + (kk + cq) * 2, t0, t1, t2, t3);
                bh[nb*2][0] = t0; bh[nb*2+1][0] = t1; bh[nb*2][1] = t2; bh[nb*2+1][1] = t3;
                ldsm4(sbase + OF_B_LO + (n0 + r16) * 80 + (kk + cq) * 2, t0, t1, t2, t3);
                bl[nb*2][0] = t0; bl[nb*2+1][0] = t1; bl[nb*2][1] = t2; bl[nb*2+1][1] = t3;
            }
#pragma unroll
            for (int ma = 0; ma < 4; ++ma)
                ldsm4(sbase + OF_A_HI + (wm*64 + ma*16 + r16) * 80 + (kk + cq) * 2,
                      ah[ma][0], ah[ma][1], ah[ma][2], ah[ma][3]);
#pragma unroll
            for (int ma = 0; ma < 4; ++ma)
#pragma unroll
                for (int na = 0; na < 4; ++na) mma16816(acc[ma][na], ah[ma], bh[na]);
#pragma unroll
            for (int ma = 0; ma < 4; ++ma)
#pragma unroll
                for (int na = 0; na < 4; ++na) mma16816(acc[ma][na], ah[ma], bl[na]);
#pragma unroll
            for (int ma = 0; ma < 4; ++ma)
                ldsm4(sbase + OF_A_LO + (wm*64 + ma*16 + r16) * 80 + (kk + cq) * 2,
                      ah[ma][0], ah[ma][1], ah[ma][2], ah[ma][3]);
#pragma unroll
            for (int ma = 0; ma < 4; ++ma)
#pragma unroll
                for (int na = 0; na < 4; ++na) mma16816(acc[ma][na], ah[ma], bh[na]);
        }
        __syncthreads();
    }

    // ====== hidden: bias + SiLU + bf16 split -> Hs (swizzled 256B rows) ====
    {
        const int rbase = lane >> 2;
        const int cp    = (lane & 3);
#pragma unroll
        for (int ma = 0; ma < 4; ++ma)
#pragma unroll
            for (int rh = 0; rh < 2; ++rh) {
                const int row = wm*64 + ma*16 + rh*8 + rbase;
#pragma unroll
                for (int na = 0; na < 4; ++na) {
                    const int col = wn*32 + na*8 + cp*2;
                    float x0 = acc[ma][na][rh*2]     + sB1[col];
                    float x1 = acc[ma][na][rh*2 + 1] + sB1[col + 1];
                    x0 = x0 / (1.f + __expf(-x0));
                    x1 = x1 / (1.f + __expf(-x1));
                    uint32_t lo, hi = pk2(x0, x1, lo);
                    const uint32_t u = (uint32_t)(wn*64 + na*16);
                    const uint32_t boff = (uint32_t)row*256u + (u ^ (((uint32_t)row & 7u) << 4)) + cp*4;
                    *(uint32_t*)(dsm + OF_HS_HI + boff) = hi;
                    *(uint32_t*)(dsm + OF_HS_LO + boff) = lo;
                    acc[ma][na][rh*2] = 0.f; acc[ma][na][rh*2 + 1] = 0.f;
                }
            }
    }
    __syncthreads();

    // ================= GEMM2: hidden [128,128] @ W2 ========================
    for (int c = 0; c < 4; ++c) {
        const int k0 = c * 32;
        {
            const int n = tid >> 1, h = tid & 1;
            const __nv_bfloat16* ph = W2hi + (size_t)n * CC + k0 + h * 16;
            const __nv_bfloat16* pl = W2lo + (size_t)n * CC + k0 + h * 16;
            char* dh = dsm + OF_B_HI + n * 80 + h * 32;
            char* dl = dsm + OF_B_LO + n * 80 + h * 32;
            *(uint4*)dh        = __ldg((const uint4*)ph);
            *(uint4*)(dh + 16) = __ldg((const uint4*)ph + 1);
            *(uint4*)dl        = __ldg((const uint4*)pl);
            *(uint4*)(dl + 16) = __ldg((const uint4*)pl + 1);
        }
        __syncthreads();

#pragma unroll
        for (int ks = 0; ks < 2; ++ks) {
            const int kk = ks * 16;
            uint32_t ah[4][4], bh[4][2], bl[4][2];
#pragma unroll
            for (int nb = 0; nb < 2; ++nb) {
                const int n0 = wn * 32 + nb * 16;
                uint32_t t0, t1, t2, t3;
                ldsm4(sbase + OF_B_HI + (n0 + r16) * 80 + (kk + cq) * 2, t0, t1, t2, t3);
                bh[nb*2][0] = t0; bh[nb*2+1][0] = t1; bh[nb*2][1] = t2; bh[nb*2+1][1] = t3;
                ldsm4(sbase + OF_B_LO + (n0 + r16) * 80 + (kk + cq) * 2, t0, t1, t2, t3);
                bl[nb*2][0] = t0; bl[nb*2+1][0] = t1; bl[nb*2][1] = t2; bl[nb*2+1][1] = t3;
            }
            const uint32_t kb = (uint32_t)((k0 + kk + cq) * 2);
#pragma unroll
            for (int ma = 0; ma < 4; ++ma) {
                const uint32_t row = (uint32_t)(wm*64 + ma*16 + r16);
                const uint32_t aoff = row*256u + (kb ^ ((row & 7u) << 4));
                ldsm4(sbase + OF_HS_HI + aoff, ah[ma][0], ah[ma][1], ah[ma][2], ah[ma][3]);
            }
#pragma unroll
            for (int ma = 0; ma < 4; ++ma)
#pragma unroll
                for (int na = 0; na < 4; ++na) mma16816(acc[ma][na], ah[ma], bh[na]);
#pragma unroll
            for (int ma = 0; ma < 4; ++ma)
#pragma unroll
                for (int na = 0; na < 4; ++na) mma16816(acc[ma][na], ah[ma], bl[na]);
#pragma unroll
            for (int ma = 0; ma < 4; ++ma) {
                const uint32_t row = (uint32_t)(wm*64 + ma*16 + r16);
                const uint32_t aoff = row*256u + (kb ^ ((row & 7u) << 4));
                ldsm4(sbase + OF_HS_LO + aoff, ah[ma][0], ah[ma][1], ah[ma][2], ah[ma][3]);
            }
#pragma unroll
            for (int ma = 0; ma < 4; ++ma)
#pragma unroll
                for (int na = 0; na < 4; ++na) mma16816(acc[ma][na], ah[ma], bh[na]);
        }
        __syncthreads();
    }

    // ================= epilogue: bias + LayerNorm (+resid / +scatter) =====
    float2* sLN = (float2*)(dsm + OF_A_HI);   // [128][4], aliases free A-chunk
    {
        const int rbase = lane >> 2;
        const int cp    = (lane & 3);
#pragma unroll
        for (int ma = 0; ma < 4; ++ma)
#pragma unroll
            for (int rh = 0; rh < 2; ++rh) {
                const int rloc = wm*64 + ma*16 + rh*8 + rbase;
                float s = 0.f, ss = 0.f;
#pragma unroll
                for (int na = 0; na < 4; ++na) {
                    const int col = wn*32 + na*8 + cp*2;
                    float y0 = acc[ma][na][rh*2]     + sB2[col];
                    float y1 = acc[ma][na][rh*2 + 1] + sB2[col + 1];
                    s += y0 + y1; ss += y0*y0 + y1*y1;
                }
                s  += __shfl_xor_sync(0xffffffffu, s, 1);
                ss += __shfl_xor_sync(0xffffffffu, ss, 1);
                s  += __shfl_xor_sync(0xffffffffu, s, 2);
                ss += __shfl_xor_sync(0xffffffffu, ss, 2);
                if (cp == 0) sLN[rloc * 4 + wn] = make_float2(s, ss);
            }
        __syncthreads();

#pragma unroll
        for (int ma = 0; ma < 4; ++ma)
#pragma unroll
            for (int rh = 0; rh < 2; ++rh) {
                const int rloc = wm*64 + ma*16 + rh*8 + rbase;
                const int row  = tile0 + rloc;
                float2 p0 = sLN[rloc*4 + 0], p1 = sLN[rloc*4 + 1];
                float2 p2 = sLN[rloc*4 + 2], p3 = sLN[rloc*4 + 3];
                const float s  = p0.x + p1.x + p2.x + p3.x;
                const float ss = p0.y + p1.y + p2.y + p3.y;
                const float mu  = s * (1.f / 128.f);
                const float var = ss * (1.f / 128.f) - mu * mu;
                const float rs  = rsqrtf(var + 1e-5f);
                if (row < M) {
                    const int d = EDGE ? saggi[rloc] : 0;
#pragma unroll
                    for (int na = 0; na < 4; ++na) {
                        const int col = wn*32 + na*8 + cp*2;
                        float y0 = acc[ma][na][rh*2]     + sB2[col];
                        float y1 = acc[ma][na][rh*2 + 1] + sB2[col + 1];
                        float v0 = (y0 - mu) * rs * sG[col]     + sBN[col];
                        float v1 = (y1 - mu) * rs * sG[col + 1] + sBN[col + 1];
                        if (!EDGE) {
                            float2 rv = *(const float2*)(resid + (size_t)row * CC + col);
                            v0 += rv.x; v1 += rv.y;
                        }
                        *(float2*)(out + (size_t)row * CC + col) = make_float2(v0, v1);
                        if (EDGE) {
                            float* ap = agg + (size_t)d * CC + col;
                            asm volatile("red.global.add.v2.f32 [%0], {%1,%2};"
                                         :: "l"(ap), "f"(v0), "f"(v1) : "memory");
                        }
                    }
                }
            }
    }
}

// -------------------- prep: transpose + bf16-split weights -----------------
__global__ void prep_kernel(const float* __restrict__ W,
                            __nv_bfloat16* __restrict__ hi,
                            __nv_bfloat16* __restrict__ lo, int K) {
    int i = blockIdx.x * blockDim.x + threadIdx.x;
    if (i >= K * CC) return;
    int k = i / CC, n = i % CC;
    float v = W[i];
    __nv_bfloat16 h = __float2bfloat16(v);
    float r = v - __bfloat162float(h);
    hi[(size_t)n * K + k] = h;
    lo[(size_t)n * K + k] = __float2bfloat16(r);
}

__global__ void zero4_kernel(float4* __restrict__ p, int n4) {
    int i = blockIdx.x * blockDim.x + threadIdx.x;
    if (i < n4) p[i] = make_float4(0.f, 0.f, 0.f, 0.f);
}

// -------------------- launch ----------------------------------------------
extern "C" void kernel_launch(void* const* d_in, const int* in_sizes, int n_in,
                              void* d_out, int out_size)
{
    const float* x_src     = (const float*)d_in[0];
    const float* x_dst     = (const float*)d_in[1];
    const float* edge_attr = (const float*)d_in[2];
    const int*   edge_idx  = (const int*)d_in[3];
    const float* ew1 = (const float*)d_in[4];
    const float* eb1 = (const float*)d_in[5];
    const float* ew2 = (const float*)d_in[6];
    const float* eb2 = (const float*)d_in[7];
    const float* eg  = (const float*)d_in[8];
    const float* ebn = (const float*)d_in[9];
    const float* nw1 = (const float*)d_in[10];
    const float* nb1 = (const float*)d_in[11];
    const float* nw2 = (const float*)d_in[12];
    const float* nb2 = (const float*)d_in[13];
    const float* ng  = (const float*)d_in[14];
    const float* nbn = (const float*)d_in[15];

    const int n_src   = in_sizes[0] / CC;
    const int n_dst   = in_sizes[1] / CC;
    const int n_edges = in_sizes[2] / CC;

    const int* src_idx = edge_idx;
    const int* dst_idx = edge_idx + n_edges;

    float* out_src  = (float*)d_out;
    float* out_dst  = out_src + (size_t)n_src * CC;
    float* out_edge = out_dst + (size_t)n_dst * CC;

    float* agg; __nv_bfloat16 *e1h, *e1l, *e2h, *e2l, *n1h, *n1l, *n2h, *n2l;
    cudaGetSymbolAddress((void**)&agg, g_agg);
    cudaGetSymbolAddress((void**)&e1h, g_e1hi); cudaGetSymbolAddress((void**)&e1l, g_e1lo);
    cudaGetSymbolAddress((void**)&e2h, g_e2hi); cudaGetSymbolAddress((void**)&e2l, g_e2lo);
    cudaGetSymbolAddress((void**)&n1h, g_n1hi); cudaGetSymbolAddress((void**)&n1l, g_n1lo);
    cudaGetSymbolAddress((void**)&n2h, g_n2hi); cudaGetSymbolAddress((void**)&n2l, g_n2lo);

    cudaFuncSetAttribute(mlp_mma<3, true>,
                         cudaFuncAttributeMaxDynamicSharedMemorySize, SMEM_BYTES);
    cudaFuncSetAttribute(mlp_mma<2, false>,
                         cudaFuncAttributeMaxDynamicSharedMemorySize, SMEM_BYTES);

    // weight prep (transpose + bf16 split)
    prep_kernel<<<(3 * CC * CC + 255) / 256, 256>>>(ew1, e1h, e1l, 3 * CC);
    prep_kernel<<<(CC * CC + 255) / 256, 256>>>(ew2, e2h, e2l, CC);
    prep_kernel<<<(2 * CC * CC + 255) / 256, 256>>>(nw1, n1h, n1l, 2 * CC);
    prep_kernel<<<(CC * CC + 255) / 256, 256>>>(nw2, n2h, n2l, CC);

    // zero aggregator
    {
        int n4 = (n_dst * CC) / 4;
        zero4_kernel<<<(n4 + 255) / 256, 256>>>((float4*)agg, n4);
    }
    // edge MLP + scatter-add into agg
    {
        int nb = (n_edges + MT - 1) / MT;
        mlp_mma<3, true><<<nb, NTH, SMEM_BYTES>>>(
            x_dst, dst_idx, x_src, src_idx, edge_attr,
            e1h, e1l, e2h, e2l, eb1, eb2, eg, ebn,
            nullptr, dst_idx, agg, out_edge, n_edges);
    }
    // dst node MLP on [x_dst | agg] + residual
    {
        int nb = (n_dst + MT - 1) / MT;
        mlp_mma<2, false><<<nb, NTH, SMEM_BYTES>>>(
            x_dst, nullptr, agg, nullptr, nullptr,
            n1h, n1l, n2h, n2l, nb1, nb2, ng, nbn,
            x_dst, nullptr, nullptr, out_dst, n_dst);
    }
    // src node MLP on [x_src | x_src] + residual
    {
        int nb = (n_src + MT - 1) / MT;
        mlp_mma<2, false><<<nb, NTH, SMEM_BYTES>>>(
            x_src, nullptr, x_src, nullptr, nullptr,
            n1h, n1l, n2h, n2l, nb1, nb2, ng, nbn,
            x_src, nullptr, nullptr, out_src, n_src);
    }
}

// round 5
// speedup vs baseline: 2.1086x; 1.0939x over previous
#include <cuda_runtime.h>
#include <cstdint>
#include <cstddef>

#define CC  128
#define MT  128
#define NTH 256

#define AST 36          // A chunk row stride (floats)
#define HST 136         // hidden plane row stride (floats)

#define OFA 0
#define OFB (128 * AST)             // 4608 floats
#define OFH (2 * 128 * AST)         // 9216 floats
#define SMEM_FLOATS (2 * 128 * AST + 128 * HST)   // 26624 floats
#define SMEM_BYTES  (SMEM_FLOATS * 4)             // 106496 B

// -------------------- device globals (no allocations allowed) --------------
__device__ float g_agg[40000 * CC];
__device__ float g_w1e[CC * 3 * CC];   // transposed [n][k], tf32-rounded
__device__ float g_w2e[CC * CC];
__device__ float g_w1n[CC * 2 * CC];
__device__ float g_w2n[CC * CC];

// -------------------- helpers ----------------------------------------------
__device__ __forceinline__ uint32_t rna(float x) {
    uint32_t u; asm("cvt.rna.tf32.f32 %0, %1;" : "=r"(u) : "f"(x)); return u;
}
__device__ __forceinline__ void mma_t(float* c, const uint32_t* a, const uint32_t* b) {
    asm volatile(
        "mma.sync.aligned.m16n8k8.row.col.f32.tf32.tf32.f32 "
        "{%0,%1,%2,%3}, {%4,%5,%6,%7}, {%8,%9}, {%0,%1,%2,%3};"
        : "+f"(c[0]), "+f"(c[1]), "+f"(c[2]), "+f"(c[3])
        : "r"(a[0]), "r"(a[1]), "r"(a[2]), "r"(a[3]), "r"(b[0]), "r"(b[1]));
}

// -------------------- fused MLP kernel (tf32 single-pass) ------------------
template<int SEGS, bool EDGE>
__global__ __launch_bounds__(NTH, 2)
void mlp_tf32(const float* __restrict__ seg0, const int* __restrict__ idx0,
              const float* __restrict__ seg1, const int* __restrict__ idx1,
              const float* __restrict__ seg2,
              const float* __restrict__ W1, const float* __restrict__ W2,
              const float* __restrict__ B1, const float* __restrict__ B2,
              const float* __restrict__ G,  const float* __restrict__ BN,
              const float* __restrict__ resid,
              const int* __restrict__ aggidx, float* __restrict__ agg,
              float* __restrict__ out, int M)
{
    extern __shared__ __align__(16) float smf[];
    __shared__ int srow[3][MT];
    __shared__ int saggi[MT];
    __shared__ float sB1[CC], sB2[CC], sG[CC], sBN[CC];

    const int tid  = threadIdx.x;
    const int wid  = tid >> 5;
    const int lane = tid & 31;
    const int wm   = wid & 1;        // 2 row-groups of 64
    const int wn   = wid >> 1;       // 4 col-groups of 32
    const int tile0 = blockIdx.x * MT;
    const int K1 = SEGS * CC;
    const int r4 = lane >> 2;
    const int c4 = lane & 3;

    if (tid < MT) {
        int r = tile0 + tid;
        int rr = (r < M) ? r : (M - 1);
        srow[0][tid] = idx0 ? idx0[rr] : rr;
        srow[1][tid] = idx1 ? idx1[rr] : rr;
        srow[2][tid] = rr;
        if (EDGE) saggi[tid] = aggidx[rr];
        sB1[tid] = B1[tid]; sB2[tid] = B2[tid];
        sG[tid]  = G[tid];  sBN[tid] = BN[tid];
    }

    float acc[4][4][4];
#pragma unroll
    for (int i = 0; i < 4; i++)
#pragma unroll
        for (int j = 0; j < 4; j++)
#pragma unroll
            for (int k = 0; k < 4; k++) acc[i][j][k] = 0.f;

    __syncthreads();

    // ================= GEMM1: [128, SEGS*128] @ W1 =========================
    for (int c = 0; c < SEGS * 4; ++c) {
        const int k0  = c * 32;
        const int sg  = k0 >> 7;
        const int off = k0 & 127;
        const float* base = (sg == 0) ? seg0 : ((sg == 1) ? seg1 : seg2);
        const int*   srw  = srow[sg];

        // ---- stage A chunk: gathered fp32, tf32-rounded, stride 36 floats
        {
            const int m = tid >> 1, h = tid & 1;
            const float* p = base + (size_t)srw[m] * CC + off + h * 16;
            float* dst = smf + OFA + m * AST + h * 16;
#pragma unroll
            for (int q = 0; q < 4; q++) {
                float4 v = __ldg((const float4*)p + q);
                uint4 u = make_uint4(rna(v.x), rna(v.y), rna(v.z), rna(v.w));
                *(uint4*)(dst + q * 4) = u;
            }
        }
        // ---- stage B chunk: prepped tf32 planes [n][K1], straight copy
        {
            const int n = tid >> 1, h = tid & 1;
            const float* pw = W1 + (size_t)n * K1 + k0 + h * 16;
            float* dst = smf + OFB + n * AST + h * 16;
#pragma unroll
            for (int q = 0; q < 4; q++)
                *(float4*)(dst + q * 4) = __ldg((const float4*)pw + q);
        }
        __syncthreads();

#pragma unroll
        for (int ks = 0; ks < 4; ++ks) {
            const int kk = ks * 8;
            uint32_t a[4][4], b[4][2];
#pragma unroll
            for (int na = 0; na < 4; ++na) {
                const int n0 = wn * 32 + na * 8 + r4;
                b[na][0] = __float_as_uint(smf[OFB + n0 * AST + kk + c4]);
                b[na][1] = __float_as_uint(smf[OFB + n0 * AST + kk + c4 + 4]);
            }
#pragma unroll
            for (int ma = 0; ma < 4; ++ma) {
                const int m0 = wm * 64 + ma * 16 + r4;
                a[ma][0] = __float_as_uint(smf[OFA + m0 * AST + kk + c4]);
                a[ma][1] = __float_as_uint(smf[OFA + (m0 + 8) * AST + kk + c4]);
                a[ma][2] = __float_as_uint(smf[OFA + m0 * AST + kk + c4 + 4]);
                a[ma][3] = __float_as_uint(smf[OFA + (m0 + 8) * AST + kk + c4 + 4]);
            }
#pragma unroll
            for (int ma = 0; ma < 4; ++ma)
#pragma unroll
                for (int na = 0; na < 4; ++na) mma_t(acc[ma][na], a[ma], b[na]);
        }
        __syncthreads();
    }

    // ====== hidden: bias + SiLU, tf32-round, store Hs[k][m] ================
    {
        uint32_t* Hf = (uint32_t*)(smf + OFH);
#pragma unroll
        for (int ma = 0; ma < 4; ++ma)
#pragma unroll
            for (int rh = 0; rh < 2; ++rh) {
                const int row = wm * 64 + ma * 16 + rh * 8 + r4;
#pragma unroll
                for (int na = 0; na < 4; ++na) {
                    const int col = wn * 32 + na * 8 + c4 * 2;
                    float x0 = acc[ma][na][rh * 2]     + sB1[col];
                    float x1 = acc[ma][na][rh * 2 + 1] + sB1[col + 1];
                    x0 = x0 / (1.f + __expf(-x0));
                    x1 = x1 / (1.f + __expf(-x1));
                    Hf[col * HST + row]       = rna(x0);
                    Hf[(col + 1) * HST + row] = rna(x1);
                    acc[ma][na][rh * 2] = 0.f; acc[ma][na][rh * 2 + 1] = 0.f;
                }
            }
    }
    __syncthreads();

    // ================= GEMM2: hidden [128,128] @ W2 ========================
    for (int c = 0; c < 4; ++c) {
        const int k0 = c * 32;
        {
            const int n = tid >> 1, h = tid & 1;
            const float* pw = W2 + (size_t)n * CC + k0 + h * 16;
            float* dst = smf + OFB + n * AST + h * 16;
#pragma unroll
            for (int q = 0; q < 4; q++)
                *(float4*)(dst + q * 4) = __ldg((const float4*)pw + q);
        }
        __syncthreads();

#pragma unroll
        for (int ks = 0; ks < 4; ++ks) {
            const int kk = k0 + ks * 8;
            uint32_t a[4][4], b[4][2];
#pragma unroll
            for (int na = 0; na < 4; ++na) {
                const int n0 = wn * 32 + na * 8 + r4;
                b[na][0] = __float_as_uint(smf[OFB + n0 * AST + ks * 8 + c4]);
                b[na][1] = __float_as_uint(smf[OFB + n0 * AST + ks * 8 + c4 + 4]);
            }
#pragma unroll
            for (int ma = 0; ma < 4; ++ma) {
                const int m0 = wm * 64 + ma * 16 + r4;
                a[ma][0] = __float_as_uint(smf[OFH + (kk + c4) * HST + m0]);
                a[ma][1] = __float_as_uint(smf[OFH + (kk + c4) * HST + m0 + 8]);
                a[ma][2] = __float_as_uint(smf[OFH + (kk + c4 + 4) * HST + m0]);
                a[ma][3] = __float_as_uint(smf[OFH + (kk + c4 + 4) * HST + m0 + 8]);
            }
#pragma unroll
            for (int ma = 0; ma < 4; ++ma)
#pragma unroll
                for (int na = 0; na < 4; ++na) mma_t(acc[ma][na], a[ma], b[na]);
        }
        __syncthreads();
    }

    // ================= epilogue: bias + LayerNorm (+resid / +scatter) =====
    float2* sLN = (float2*)(smf + OFA);   // aliases dead A-chunk buffer
    {
#pragma unroll
        for (int ma = 0; ma < 4; ++ma)
#pragma unroll
            for (int rh = 0; rh < 2; ++rh) {
                const int rloc = wm * 64 + ma * 16 + rh * 8 + r4;
                float s = 0.f, ss = 0.f;
#pragma unroll
                for (int na = 0; na < 4; ++na) {
                    const int col = wn * 32 + na * 8 + c4 * 2;
                    float y0 = acc[ma][na][rh * 2]     + sB2[col];
                    float y1 = acc[ma][na][rh * 2 + 1] + sB2[col + 1];
                    s += y0 + y1; ss += y0 * y0 + y1 * y1;
                }
                s  += __shfl_xor_sync(0xffffffffu, s, 1);
                ss += __shfl_xor_sync(0xffffffffu, ss, 1);
                s  += __shfl_xor_sync(0xffffffffu, s, 2);
                ss += __shfl_xor_sync(0xffffffffu, ss, 2);
                if (c4 == 0) sLN[rloc * 4 + wn] = make_float2(s, ss);
            }
        __syncthreads();

#pragma unroll
        for (int ma = 0; ma < 4; ++ma)
#pragma unroll
            for (int rh = 0; rh < 2; ++rh) {
                const int rloc = wm * 64 + ma * 16 + rh * 8 + r4;
                const int row  = tile0 + rloc;
                float2 p0 = sLN[rloc * 4 + 0], p1 = sLN[rloc * 4 + 1];
                float2 p2 = sLN[rloc * 4 + 2], p3 = sLN[rloc * 4 + 3];
                const float s  = p0.x + p1.x + p2.x + p3.x;
                const float ss = p0.y + p1.y + p2.y + p3.y;
                const float mu  = s * (1.f / 128.f);
                const float var = ss * (1.f / 128.f) - mu * mu;
                const float rs  = rsqrtf(var + 1e-5f);
                if (row < M) {
                    const int d = EDGE ? saggi[rloc] : 0;
#pragma unroll
                    for (int na = 0; na < 4; ++na) {
                        const int col = wn * 32 + na * 8 + c4 * 2;
                        float y0 = acc[ma][na][rh * 2]     + sB2[col];
                        float y1 = acc[ma][na][rh * 2 + 1] + sB2[col + 1];
                        float v0 = (y0 - mu) * rs * sG[col]     + sBN[col];
                        float v1 = (y1 - mu) * rs * sG[col + 1] + sBN[col + 1];
                        if (!EDGE) {
                            float2 rv = *(const float2*)(resid + (size_t)row * CC + col);
                            v0 += rv.x; v1 += rv.y;
                        }
                        *(float2*)(out + (size_t)row * CC + col) = make_float2(v0, v1);
                        if (EDGE) {
                            float* ap = agg + (size_t)d * CC + col;
                            asm volatile("red.global.add.v2.f32 [%0], {%1,%2};"
                                         :: "l"(ap), "f"(v0), "f"(v1) : "memory");
                        }
                    }
                }
            }
    }
}

// ---- fused setup: zero agg + transpose/round all weight planes ------------
__global__ void setup_kernel(const float* __restrict__ ew1, const float* __restrict__ ew2,
                             const float* __restrict__ nw1, const float* __restrict__ nw2,
                             int n4)
{
    const int gid = blockIdx.x * blockDim.x + threadIdx.x;
    if (gid < n4) ((float4*)g_agg)[gid] = make_float4(0.f, 0.f, 0.f, 0.f);
    if (gid < 7 * CC * CC) {
        int i = gid;
        if (i < 3 * CC * CC) {
            int k = i / CC, n = i % CC;
            g_w1e[n * 3 * CC + k] = __uint_as_float(rna(ew1[i]));
        } else if (i < 4 * CC * CC) {
            int j = i - 3 * CC * CC; int k = j / CC, n = j % CC;
            g_w2e[n * CC + k] = __uint_as_float(rna(ew2[j]));
        } else if (i < 6 * CC * CC) {
            int j = i - 4 * CC * CC; int k = j / CC, n = j % CC;
            g_w1n[n * 2 * CC + k] = __uint_as_float(rna(nw1[j]));
        } else {
            int j = i - 6 * CC * CC; int k = j / CC, n = j % CC;
            g_w2n[n * CC + k] = __uint_as_float(rna(nw2[j]));
        }
    }
}

// -------------------- launch ----------------------------------------------
extern "C" void kernel_launch(void* const* d_in, const int* in_sizes, int n_in,
                              void* d_out, int out_size)
{
    const float* x_src     = (const float*)d_in[0];
    const float* x_dst     = (const float*)d_in[1];
    const float* edge_attr = (const float*)d_in[2];
    const int*   edge_idx  = (const int*)d_in[3];
    const float* ew1 = (const float*)d_in[4];
    const float* eb1 = (const float*)d_in[5];
    const float* ew2 = (const float*)d_in[6];
    const float* eb2 = (const float*)d_in[7];
    const float* eg  = (const float*)d_in[8];
    const float* ebn = (const float*)d_in[9];
    const float* nw1 = (const float*)d_in[10];
    const float* nb1 = (const float*)d_in[11];
    const float* nw2 = (const float*)d_in[12];
    const float* nb2 = (const float*)d_in[13];
    const float* ng  = (const float*)d_in[14];
    const float* nbn = (const float*)d_in[15];

    const int n_src   = in_sizes[0] / CC;
    const int n_dst   = in_sizes[1] / CC;
    const int n_edges = in_sizes[2] / CC;

    const int* src_idx = edge_idx;
    const int* dst_idx = edge_idx + n_edges;

    float* out_src  = (float*)d_out;
    float* out_dst  = out_src + (size_t)n_src * CC;
    float* out_edge = out_dst + (size_t)n_dst * CC;

    float *agg, *w1e, *w2e, *w1n, *w2n;
    cudaGetSymbolAddress((void**)&agg, g_agg);
    cudaGetSymbolAddress((void**)&w1e, g_w1e);
    cudaGetSymbolAddress((void**)&w2e, g_w2e);
    cudaGetSymbolAddress((void**)&w1n, g_w1n);
    cudaGetSymbolAddress((void**)&w2n, g_w2n);

    cudaFuncSetAttribute(mlp_tf32<3, true>,
                         cudaFuncAttributeMaxDynamicSharedMemorySize, SMEM_BYTES);
    cudaFuncSetAttribute(mlp_tf32<2, false>,
                         cudaFuncAttributeMaxDynamicSharedMemorySize, SMEM_BYTES);

    // 1) fused setup: zero agg + weight transpose/round (1 launch)
    {
        int n4 = (n_dst * CC) / 4;
        int nthreads = n4 > 7 * CC * CC ? n4 : 7 * CC * CC;
        setup_kernel<<<(nthreads + 255) / 256, 256>>>(ew1, ew2, nw1, nw2, n4);
    }
    // 2) edge MLP + scatter-add into agg
    {
        int nb = (n_edges + MT - 1) / MT;
        mlp_tf32<3, true><<<nb, NTH, SMEM_BYTES>>>(
            x_dst, dst_idx, x_src, src_idx, edge_attr,
            w1e, w2e, eb1, eb2, eg, ebn,
            nullptr, dst_idx, agg, out_edge, n_edges);
    }
    // 3) dst node MLP on [x_dst | agg] + residual
    {
        int nb = (n_dst + MT - 1) / MT;
        mlp_tf32<2, false><<<nb, NTH, SMEM_BYTES>>>(
            x_dst, nullptr, agg, nullptr, nullptr,
            w1n, w2n, nb1, nb2, ng, nbn,
            x_dst, nullptr, nullptr, out_dst, n_dst);
    }
    // 4) src node MLP on [x_src | x_src] + residual
    {
        int nb = (n_src + MT - 1) / MT;
        mlp_tf32<2, false><<<nb, NTH, SMEM_BYTES>>>(
            x_src, nullptr, x_src, nullptr, nullptr,
            w1n, w2n, nb1, nb2, ng, nbn,
            x_src, nullptr, nullptr, out_src, n_src);
    }
}